// round 1
// baseline (speedup 1.0000x reference)
#include <cuda_runtime.h>

// Problem constants
#define N_PTS   65536
#define C_DIM   512
#define H_HEADS 8
#define P_WIN   128
#define DHEAD   64
#define W_WIN   (N_PTS / P_WIN)     // 512 windows
#define RPE_NUM 31
#define POS_BND 15
#define SCALE_F 0.125f              // DH^-0.5 = 64^-0.5

// Scratch (device globals: allocation-free per harness rules)
__device__ float g_qkv[(size_t)N_PTS * 3 * C_DIM];   // serialized order, [N, 3C]
__device__ float g_attn[(size_t)N_PTS * C_DIM];      // point order (scatter done in attention epilogue)

// ---------------------------------------------------------------------------
// GEMM (NT): C[m,n] = sum_k A[g(m),k] * B[n,k] + bias[n]
// A: [M,K] row-major (rows optionally gathered), B: [N,K] row-major.
// 128x128 block tile, BK=16, 256 threads, 8x8 per-thread microtile.
// ---------------------------------------------------------------------------
__global__ void __launch_bounds__(256) gemm_nt_kernel(
    const float* __restrict__ A, const float* __restrict__ B,
    const float* __restrict__ bias, float* __restrict__ C,
    int M, int N, int K, const int* __restrict__ gather)
{
    __shared__ __align__(16) float As[16][128];
    __shared__ __align__(16) float Bs[16][128];

    const int tid = threadIdx.x;
    const int tx  = tid & 15;       // column group
    const int ty  = tid >> 4;       // row group

    // Loader mapping: 512 float4 per tile per matrix; 2 per thread.
    int a_row[2], a_k[2];
    const float* a_ptr[2];
    const float* b_ptr[2];
#pragma unroll
    for (int i = 0; i < 2; ++i) {
        int idx = tid + i * 256;
        int row = idx >> 2;         // 0..127
        int k4  = idx & 3;          // 0..3  (k offset = k4*4)
        a_row[i] = row;
        a_k[i]   = k4 * 4;
        int gr = blockIdx.y * 128 + row;
        if (gather) gr = gather[gr];
        a_ptr[i] = A + (size_t)gr * K + k4 * 4;
        b_ptr[i] = B + (size_t)(blockIdx.x * 128 + row) * K + k4 * 4;
    }

    float acc[8][8];
#pragma unroll
    for (int i = 0; i < 8; ++i)
#pragma unroll
        for (int j = 0; j < 8; ++j) acc[i][j] = 0.f;

    for (int kt = 0; kt < K; kt += 16) {
#pragma unroll
        for (int i = 0; i < 2; ++i) {
            float4 va = *(const float4*)(a_ptr[i] + kt);
            As[a_k[i] + 0][a_row[i]] = va.x;
            As[a_k[i] + 1][a_row[i]] = va.y;
            As[a_k[i] + 2][a_row[i]] = va.z;
            As[a_k[i] + 3][a_row[i]] = va.w;
            float4 vb = *(const float4*)(b_ptr[i] + kt);
            Bs[a_k[i] + 0][a_row[i]] = vb.x;
            Bs[a_k[i] + 1][a_row[i]] = vb.y;
            Bs[a_k[i] + 2][a_row[i]] = vb.z;
            Bs[a_k[i] + 3][a_row[i]] = vb.w;
        }
        __syncthreads();
#pragma unroll
        for (int kk = 0; kk < 16; ++kk) {
            float4 a0 = *(const float4*)&As[kk][ty * 8];
            float4 a1 = *(const float4*)&As[kk][ty * 8 + 4];
            float4 b0 = *(const float4*)&Bs[kk][tx * 8];
            float4 b1 = *(const float4*)&Bs[kk][tx * 8 + 4];
            float ar[8] = {a0.x, a0.y, a0.z, a0.w, a1.x, a1.y, a1.z, a1.w};
            float br[8] = {b0.x, b0.y, b0.z, b0.w, b1.x, b1.y, b1.z, b1.w};
#pragma unroll
            for (int i = 0; i < 8; ++i)
#pragma unroll
                for (int j = 0; j < 8; ++j)
                    acc[i][j] += ar[i] * br[j];
        }
        __syncthreads();
    }

    // Epilogue
    const int col0 = blockIdx.x * 128 + tx * 8;
    float bb[8];
#pragma unroll
    for (int j = 0; j < 8; ++j) bb[j] = bias[col0 + j];

#pragma unroll
    for (int i = 0; i < 8; ++i) {
        int row = blockIdx.y * 128 + ty * 8 + i;
        float* cptr = C + (size_t)row * N + col0;
        float4 o0, o1;
        o0.x = acc[i][0] + bb[0]; o0.y = acc[i][1] + bb[1];
        o0.z = acc[i][2] + bb[2]; o0.w = acc[i][3] + bb[3];
        o1.x = acc[i][4] + bb[4]; o1.y = acc[i][5] + bb[5];
        o1.z = acc[i][6] + bb[6]; o1.w = acc[i][7] + bb[7];
        *(float4*)(cptr)     = o0;
        *(float4*)(cptr + 4) = o1;
    }
}

// ---------------------------------------------------------------------------
// Windowed attention with RPE bias.
// One block per (window, head): 4096 blocks, 128 threads (thread = query row).
// Online softmax (lazy rescale), K/V streamed via smem in 32-row chunks.
// Epilogue scatters to point order (fold of `inverse`), so proj GEMM is plain.
// ---------------------------------------------------------------------------
__global__ void __launch_bounds__(128) attn_kernel(
    const float* __restrict__ qkv,        // [N, 3C] serialized
    const int*   __restrict__ grid_coord, // [N, 3] point order
    const int*   __restrict__ order,      // [N]
    const float* __restrict__ rpe,        // [3*RPE_NUM, H]
    float*       __restrict__ outp)       // [N, C] point order
{
    const int w = blockIdx.x >> 3;   // window
    const int h = blockIdx.x & 7;    // head
    const int p = threadIdx.x;       // query row within window

    __shared__ __align__(16) float ks[32][64];
    __shared__ __align__(16) float vs[32][64];
    __shared__ int   gcs[P_WIN][3];
    __shared__ float rpe_s[3 * RPE_NUM];

    const int r = w * P_WIN + p;     // serialized row
    const int o = order[r];          // point index (scatter target)

    const int gx = grid_coord[o * 3 + 0];
    const int gy = grid_coord[o * 3 + 1];
    const int gz = grid_coord[o * 3 + 2];
    gcs[p][0] = gx; gcs[p][1] = gy; gcs[p][2] = gz;
    if (p < 3 * RPE_NUM) rpe_s[p] = rpe[p * H_HEADS + h];

    // Load & pre-scale q row into registers
    float q[64];
    {
        const float* qb = qkv + (size_t)r * (3 * C_DIM) + h * DHEAD;
#pragma unroll
        for (int d4 = 0; d4 < 16; ++d4) {
            float4 v = *(const float4*)(qb + d4 * 4);
            q[d4 * 4 + 0] = v.x * SCALE_F;
            q[d4 * 4 + 1] = v.y * SCALE_F;
            q[d4 * 4 + 2] = v.z * SCALE_F;
            q[d4 * 4 + 3] = v.w * SCALE_F;
        }
    }

    float m = -1e30f, l = 0.f;
    float out[64];
#pragma unroll
    for (int d = 0; d < 64; ++d) out[d] = 0.f;

    for (int c = 0; c < 4; ++c) {
        __syncthreads();   // prev chunk consumed (and gcs/rpe_s ready on c==0)
#pragma unroll
        for (int i = 0; i < 4; ++i) {
            int idx = i * 128 + p;          // 0..511 float4 slots
            int row = idx >> 4;             // 0..31
            int c4  = idx & 15;             // 0..15
            const float* kb = qkv + (size_t)(w * P_WIN + c * 32 + row) * (3 * C_DIM)
                            + C_DIM + h * DHEAD + c4 * 4;
            *(float4*)&ks[row][c4 * 4] = *(const float4*)kb;
            *(float4*)&vs[row][c4 * 4] = *(const float4*)(kb + C_DIM);
        }
        __syncthreads();

        for (int j = 0; j < 32; ++j) {
            const int kidx = c * 32 + j;
            int dx = gx - gcs[kidx][0];
            int dy = gy - gcs[kidx][1];
            int dz = gz - gcs[kidx][2];
            dx = min(max(dx, -POS_BND), POS_BND) + POS_BND;
            dy = min(max(dy, -POS_BND), POS_BND) + POS_BND;
            dz = min(max(dz, -POS_BND), POS_BND) + POS_BND;
            float s = rpe_s[dx] + rpe_s[RPE_NUM + dy] + rpe_s[2 * RPE_NUM + dz];
#pragma unroll
            for (int d4 = 0; d4 < 16; ++d4) {
                float4 kv = *(const float4*)&ks[j][d4 * 4];
                s += q[d4 * 4 + 0] * kv.x + q[d4 * 4 + 1] * kv.y
                   + q[d4 * 4 + 2] * kv.z + q[d4 * 4 + 3] * kv.w;
            }
            float pj;
            if (s <= m) {
                pj = __expf(s - m);
            } else {
                float corr = __expf(m - s);    // exp(-1e30-s) == 0 on first hit
                l *= corr;
#pragma unroll
                for (int d = 0; d < 64; ++d) out[d] *= corr;
                m = s;
                pj = 1.f;
            }
            l += pj;
#pragma unroll
            for (int d4 = 0; d4 < 16; ++d4) {
                float4 vv = *(const float4*)&vs[j][d4 * 4];
                out[d4 * 4 + 0] += pj * vv.x;
                out[d4 * 4 + 1] += pj * vv.y;
                out[d4 * 4 + 2] += pj * vv.z;
                out[d4 * 4 + 3] += pj * vv.w;
            }
        }
    }

    const float inv = 1.f / l;
    float* ob = outp + (size_t)o * C_DIM + h * DHEAD;   // scatter to point order
#pragma unroll
    for (int d4 = 0; d4 < 16; ++d4) {
        float4 v;
        v.x = out[d4 * 4 + 0] * inv;
        v.y = out[d4 * 4 + 1] * inv;
        v.z = out[d4 * 4 + 2] * inv;
        v.w = out[d4 * 4 + 3] * inv;
        *(float4*)(ob + d4 * 4) = v;
    }
}

// ---------------------------------------------------------------------------
// Launch
// ---------------------------------------------------------------------------
extern "C" void kernel_launch(void* const* d_in, const int* in_sizes, int n_in,
                              void* d_out, int out_size)
{
    const float* feat   = (const float*)d_in[0];   // [N, C]
    const float* w_qkv  = (const float*)d_in[1];   // [3C, C]
    const float* b_qkv  = (const float*)d_in[2];   // [3C]
    const float* w_proj = (const float*)d_in[3];   // [C, C]
    const float* b_proj = (const float*)d_in[4];   // [C]
    const float* rpe    = (const float*)d_in[5];   // [3*RPE_NUM, H]
    const int*   gcoord = (const int*)d_in[6];     // [N, 3]
    const int*   order  = (const int*)d_in[7];     // [N]
    // d_in[8] = inverse: unused (fold: attention scatters via order)
    float* out = (float*)d_out;                    // [N, C]

    float *qkv_buf = nullptr, *attn_buf = nullptr;
    cudaGetSymbolAddress((void**)&qkv_buf,  g_qkv);
    cudaGetSymbolAddress((void**)&attn_buf, g_attn);

    // 1) QKV projection with fused gather: g_qkv[r,:] = feat[order[r],:] @ w_qkv^T + b
    gemm_nt_kernel<<<dim3(3 * C_DIM / 128, N_PTS / 128), 256>>>(
        feat, w_qkv, b_qkv, qkv_buf, N_PTS, 3 * C_DIM, C_DIM, order);

    // 2) Windowed attention + RPE + softmax, scatter-to-point-order epilogue
    attn_kernel<<<W_WIN * H_HEADS, 128>>>(qkv_buf, gcoord, order, rpe, attn_buf);

    // 3) Output projection (plain NT GEMM)
    gemm_nt_kernel<<<dim3(C_DIM / 128, N_PTS / 128), 256>>>(
        attn_buf, w_proj, b_proj, out, N_PTS, C_DIM, C_DIM, nullptr);
}

// round 5
// speedup vs baseline: 1.7900x; 1.7900x over previous
#include <cuda_runtime.h>
#include <cuda_bf16.h>
#include <cstdint>

// ---------------------------------------------------------------------------
// Problem constants
// ---------------------------------------------------------------------------
#define N_PTS   65536
#define C_DIM   512
#define H_HEADS 8
#define P_WIN   128
#define DHEAD   64
#define W_WIN   (N_PTS / P_WIN)
#define RPE_NUM 31
#define POS_BND 15
#define SCALE_F 0.125f

// GEMM tiling (mma.sync HMMA path; tcgen05 unavailable: harness targets sm_100 base)
#define MT   128
#define NTL  128
#define BK   16           // bf16 elems per K chunk (32 B/row)
#define KTOT 512
#define NCHUNK (KTOT / BK)        // 32
#define AW   12           // padded row stride in uint32 words (8 data + 4 pad)
// per-stage variant offsets in bytes (each tile: 128 rows * 12 words * 4B = 6144B)
#define OFF_AH 0
#define OFF_AL 6144
#define OFF_BH 12288
#define OFF_BL 18432
#define BUF_BYTES 24576
#define SMEM_DYN (2 * BUF_BYTES)   // 49152 = 48KB, no FuncSetAttribute needed

// ---------------------------------------------------------------------------
// Scratch (device globals: allocation-free)
// ---------------------------------------------------------------------------
__device__ float g_qkv[(size_t)N_PTS * 3 * C_DIM];                       // serialized [N, 3C]
__device__ __align__(16) __nv_bfloat16 g_feat_hi[(size_t)N_PTS * C_DIM];
__device__ __align__(16) __nv_bfloat16 g_feat_lo[(size_t)N_PTS * C_DIM];
__device__ __align__(16) __nv_bfloat16 g_attn_hi[(size_t)N_PTS * C_DIM]; // point order
__device__ __align__(16) __nv_bfloat16 g_attn_lo[(size_t)N_PTS * C_DIM];
__device__ __align__(16) __nv_bfloat16 g_wqkv_hi[3 * C_DIM * C_DIM];
__device__ __align__(16) __nv_bfloat16 g_wqkv_lo[3 * C_DIM * C_DIM];
__device__ __align__(16) __nv_bfloat16 g_wproj_hi[C_DIM * C_DIM];
__device__ __align__(16) __nv_bfloat16 g_wproj_lo[C_DIM * C_DIM];

// ---------------------------------------------------------------------------
// Helpers
// ---------------------------------------------------------------------------
__device__ __forceinline__ uint32_t smem_u32(const void* p) {
    uint32_t a;
    asm("{ .reg .u64 t; cvta.to.shared.u64 t, %1; cvt.u32.u64 %0, t; }" : "=r"(a) : "l"(p));
    return a;
}
__device__ __forceinline__ void cp16(uint32_t dst, const void* src) {
    asm volatile("cp.async.cg.shared.global [%0], [%1], 16;" :: "r"(dst), "l"(src));
}
__device__ __forceinline__ void cp_commit() { asm volatile("cp.async.commit_group;" ::: "memory"); }
template <int NN>
__device__ __forceinline__ void cp_wait() { asm volatile("cp.async.wait_group %0;" :: "n"(NN) : "memory"); }

// mma.sync m16n8k16 bf16 -> f32, accumulate in place
__device__ __forceinline__ void mma16816(float* c, const uint32_t* a, const uint32_t* b) {
    asm volatile(
        "mma.sync.aligned.m16n8k16.row.col.f32.bf16.bf16.f32 "
        "{%0,%1,%2,%3}, {%4,%5,%6,%7}, {%8,%9}, {%0,%1,%2,%3};"
        : "+f"(c[0]), "+f"(c[1]), "+f"(c[2]), "+f"(c[3])
        : "r"(a[0]), "r"(a[1]), "r"(a[2]), "r"(a[3]), "r"(b[0]), "r"(b[1]));
}

__device__ __forceinline__ uint32_t pack2(__nv_bfloat16 a, __nv_bfloat16 b) {
    return (uint32_t)__bfloat16_as_ushort(a) | ((uint32_t)__bfloat16_as_ushort(b) << 16);
}

// ---------------------------------------------------------------------------
// fp32 -> bf16 hi/lo split
// ---------------------------------------------------------------------------
__global__ void split_bf16_kernel(const float4* __restrict__ src,
                                  uint2* __restrict__ hi, uint2* __restrict__ lo, int n4)
{
    for (int i = blockIdx.x * blockDim.x + threadIdx.x; i < n4; i += gridDim.x * blockDim.x) {
        float4 v = src[i];
        __nv_bfloat16 h0 = __float2bfloat16(v.x), h1 = __float2bfloat16(v.y);
        __nv_bfloat16 h2 = __float2bfloat16(v.z), h3 = __float2bfloat16(v.w);
        __nv_bfloat16 l0 = __float2bfloat16(v.x - __bfloat162float(h0));
        __nv_bfloat16 l1 = __float2bfloat16(v.y - __bfloat162float(h1));
        __nv_bfloat16 l2 = __float2bfloat16(v.z - __bfloat162float(h2));
        __nv_bfloat16 l3 = __float2bfloat16(v.w - __bfloat162float(h3));
        hi[i] = make_uint2(pack2(h0, h1), pack2(h2, h3));
        lo[i] = make_uint2(pack2(l0, l1), pack2(l2, l3));
    }
}

// ---------------------------------------------------------------------------
// HMMA split-bf16 GEMM (NT): C[m,n] = sum_k A[g(m),k]*B[n,k] + bias[n]
// 128x128 CTA tile, BK=16, 256 threads (8 warps, 2M x 4N), warp tile 64x32.
// Double-buffered cp.async (48KB total). 3 products: AhBh + AhBl + AlBh.
// ---------------------------------------------------------------------------
__device__ __forceinline__ void load_chunk(
    uint32_t bufbase, int kc, int t, int arow, int brow,
    const __nv_bfloat16* __restrict__ Ah, const __nv_bfloat16* __restrict__ Al,
    const __nv_bfloat16* __restrict__ Bh, const __nv_bfloat16* __restrict__ Bl)
{
    // per variant: 128 rows x 2 granules of 16B = 256 granules; 1 per thread
    const int g16 = t & 1;                 // 0..1
    const uint32_t soff = (uint32_t)((t >> 1) * (AW * 4) + g16 * 16);
    const size_t goffA = (size_t)arow * KTOT + kc * BK + g16 * 8;
    const size_t goffB = (size_t)brow * KTOT + kc * BK + g16 * 8;
    cp16(bufbase + OFF_AH + soff, Ah + goffA);
    cp16(bufbase + OFF_AL + soff, Al + goffA);
    cp16(bufbase + OFF_BH + soff, Bh + goffB);
    cp16(bufbase + OFF_BL + soff, Bl + goffB);
}

__global__ void __launch_bounds__(256) gemm_tc_kernel(
    const __nv_bfloat16* __restrict__ Ah, const __nv_bfloat16* __restrict__ Al,
    const __nv_bfloat16* __restrict__ Bh, const __nv_bfloat16* __restrict__ Bl,
    const float* __restrict__ bias, float* __restrict__ C,
    int Nglob, const int* __restrict__ gather)
{
    extern __shared__ __align__(16) char dsm[];
    const uint32_t sbase = smem_u32(dsm);
    const int t = threadIdx.x;
    const int bx = blockIdx.x, by = blockIdx.y;
    const int lane = t & 31, wid = t >> 5;
    const int wm = wid & 1;          // 0..1 -> 64-row slab
    const int wn = wid >> 1;         // 0..3 -> 32-col slab
    const int g  = lane >> 2;        // 0..7
    const int tg = lane & 3;         // 0..3

    int m = by * MT + (t >> 1);
    const int arow = gather ? __ldg(gather + m) : m;
    const int brow = bx * NTL + (t >> 1);

    float acc[4][4][4];
#pragma unroll
    for (int i = 0; i < 4; ++i)
#pragma unroll
        for (int j = 0; j < 4; ++j)
#pragma unroll
            for (int e = 0; e < 4; ++e) acc[i][j][e] = 0.f;

    load_chunk(sbase, 0, t, arow, brow, Ah, Al, Bh, Bl);
    cp_commit();

    for (int c = 0; c < NCHUNK; ++c) {
        if (c + 1 < NCHUNK) {
            load_chunk(sbase + ((c + 1) & 1) * BUF_BYTES, c + 1, t, arow, brow, Ah, Al, Bh, Bl);
            cp_commit();
            cp_wait<1>();
        } else {
            cp_wait<0>();
        }
        __syncthreads();

        const uint32_t* As_h = (const uint32_t*)(dsm + (c & 1) * BUF_BYTES + OFF_AH);
        const uint32_t* As_l = (const uint32_t*)(dsm + (c & 1) * BUF_BYTES + OFF_AL);
        const uint32_t* Bs_h = (const uint32_t*)(dsm + (c & 1) * BUF_BYTES + OFF_BH);
        const uint32_t* Bs_l = (const uint32_t*)(dsm + (c & 1) * BUF_BYTES + OFF_BL);

        // B fragments for this warp's 4 n-tiles (hi & lo)
        uint32_t bh[4][2], bl[4][2];
#pragma unroll
        for (int j = 0; j < 4; ++j) {
            int n = wn * 32 + j * 8 + g;
            bh[j][0] = Bs_h[n * AW + tg];
            bh[j][1] = Bs_h[n * AW + tg + 4];
            bl[j][0] = Bs_l[n * AW + tg];
            bl[j][1] = Bs_l[n * AW + tg + 4];
        }
#pragma unroll
        for (int i = 0; i < 4; ++i) {
            int r0 = wm * 64 + i * 16 + g;
            uint32_t ah[4], al[4];
            ah[0] = As_h[r0 * AW + tg];
            ah[1] = As_h[(r0 + 8) * AW + tg];
            ah[2] = As_h[r0 * AW + tg + 4];
            ah[3] = As_h[(r0 + 8) * AW + tg + 4];
            al[0] = As_l[r0 * AW + tg];
            al[1] = As_l[(r0 + 8) * AW + tg];
            al[2] = As_l[r0 * AW + tg + 4];
            al[3] = As_l[(r0 + 8) * AW + tg + 4];
#pragma unroll
            for (int j = 0; j < 4; ++j) {
                mma16816(acc[i][j], ah, bh[j]);
                mma16816(acc[i][j], ah, bl[j]);
                mma16816(acc[i][j], al, bh[j]);
            }
        }
        __syncthreads();   // compute done before next iter overwrites this buffer
    }

    // Epilogue: c frag layout rows {g, g+8}, cols {tg*2, tg*2+1}
#pragma unroll
    for (int i = 0; i < 4; ++i) {
        const int row0 = by * MT + wm * 64 + i * 16 + g;
#pragma unroll
        for (int j = 0; j < 4; ++j) {
            const int col = bx * NTL + wn * 32 + j * 8 + tg * 2;
            const float b0 = __ldg(bias + col), b1 = __ldg(bias + col + 1);
            float2 v0 = make_float2(acc[i][j][0] + b0, acc[i][j][1] + b1);
            float2 v1 = make_float2(acc[i][j][2] + b0, acc[i][j][3] + b1);
            *(float2*)(C + (size_t)row0 * Nglob + col) = v0;
            *(float2*)(C + (size_t)(row0 + 8) * Nglob + col) = v1;
        }
    }
}

// ---------------------------------------------------------------------------
// Windowed attention with RPE; epilogue writes bf16 hi/lo in point order.
// ---------------------------------------------------------------------------
__global__ void __launch_bounds__(128) attn_kernel(
    const float* __restrict__ qkv,        // [N, 3C] serialized
    const int*   __restrict__ grid_coord, // [N, 3] point order
    const int*   __restrict__ order,      // [N]
    const float* __restrict__ rpe)        // [3*RPE_NUM, H]
{
    const int w = blockIdx.x >> 3;
    const int h = blockIdx.x & 7;
    const int p = threadIdx.x;

    __shared__ __align__(16) float ks[32][64];
    __shared__ __align__(16) float vs[32][64];
    __shared__ int   gcs[P_WIN][3];
    __shared__ float rpe_s[3 * RPE_NUM];

    const int r = w * P_WIN + p;
    const int o = order[r];

    const int gx = grid_coord[o * 3 + 0];
    const int gy = grid_coord[o * 3 + 1];
    const int gz = grid_coord[o * 3 + 2];
    gcs[p][0] = gx; gcs[p][1] = gy; gcs[p][2] = gz;
    if (p < 3 * RPE_NUM) rpe_s[p] = rpe[p * H_HEADS + h];

    float q[64];
    {
        const float* qb = qkv + (size_t)r * (3 * C_DIM) + h * DHEAD;
#pragma unroll
        for (int d4 = 0; d4 < 16; ++d4) {
            float4 v = *(const float4*)(qb + d4 * 4);
            q[d4 * 4 + 0] = v.x * SCALE_F;
            q[d4 * 4 + 1] = v.y * SCALE_F;
            q[d4 * 4 + 2] = v.z * SCALE_F;
            q[d4 * 4 + 3] = v.w * SCALE_F;
        }
    }

    float m = -1e30f, l = 0.f;
    float out[64];
#pragma unroll
    for (int d = 0; d < 64; ++d) out[d] = 0.f;

    for (int c = 0; c < 4; ++c) {
        __syncthreads();
#pragma unroll
        for (int i = 0; i < 4; ++i) {
            int idx = i * 128 + p;
            int row = idx >> 4;
            int c4  = idx & 15;
            const float* kb = qkv + (size_t)(w * P_WIN + c * 32 + row) * (3 * C_DIM)
                            + C_DIM + h * DHEAD + c4 * 4;
            *(float4*)&ks[row][c4 * 4] = *(const float4*)kb;
            *(float4*)&vs[row][c4 * 4] = *(const float4*)(kb + C_DIM);
        }
        __syncthreads();

        for (int j = 0; j < 32; ++j) {
            const int kidx = c * 32 + j;
            int dx = gx - gcs[kidx][0];
            int dy = gy - gcs[kidx][1];
            int dz = gz - gcs[kidx][2];
            dx = min(max(dx, -POS_BND), POS_BND) + POS_BND;
            dy = min(max(dy, -POS_BND), POS_BND) + POS_BND;
            dz = min(max(dz, -POS_BND), POS_BND) + POS_BND;
            float s = rpe_s[dx] + rpe_s[RPE_NUM + dy] + rpe_s[2 * RPE_NUM + dz];
#pragma unroll
            for (int d4 = 0; d4 < 16; ++d4) {
                float4 kv = *(const float4*)&ks[j][d4 * 4];
                s += q[d4 * 4 + 0] * kv.x + q[d4 * 4 + 1] * kv.y
                   + q[d4 * 4 + 2] * kv.z + q[d4 * 4 + 3] * kv.w;
            }
            float pj;
            if (s <= m) {
                pj = __expf(s - m);
            } else {
                float corr = __expf(m - s);
                l *= corr;
#pragma unroll
                for (int d = 0; d < 64; ++d) out[d] *= corr;
                m = s;
                pj = 1.f;
            }
            l += pj;
#pragma unroll
            for (int d4 = 0; d4 < 16; ++d4) {
                float4 vv = *(const float4*)&vs[j][d4 * 4];
                out[d4 * 4 + 0] += pj * vv.x;
                out[d4 * 4 + 1] += pj * vv.y;
                out[d4 * 4 + 2] += pj * vv.z;
                out[d4 * 4 + 3] += pj * vv.w;
            }
        }
    }

    const float inv = 1.f / l;
    uint2* obh = (uint2*)(g_attn_hi + (size_t)o * C_DIM + h * DHEAD);
    uint2* obl = (uint2*)(g_attn_lo + (size_t)o * C_DIM + h * DHEAD);
#pragma unroll
    for (int d4 = 0; d4 < 16; ++d4) {
        float v0 = out[d4 * 4 + 0] * inv;
        float v1 = out[d4 * 4 + 1] * inv;
        float v2 = out[d4 * 4 + 2] * inv;
        float v3 = out[d4 * 4 + 3] * inv;
        __nv_bfloat16 h0 = __float2bfloat16(v0), h1 = __float2bfloat16(v1);
        __nv_bfloat16 h2 = __float2bfloat16(v2), h3 = __float2bfloat16(v3);
        __nv_bfloat16 l0 = __float2bfloat16(v0 - __bfloat162float(h0));
        __nv_bfloat16 l1 = __float2bfloat16(v1 - __bfloat162float(h1));
        __nv_bfloat16 l2 = __float2bfloat16(v2 - __bfloat162float(h2));
        __nv_bfloat16 l3 = __float2bfloat16(v3 - __bfloat162float(h3));
        obh[d4] = make_uint2(pack2(h0, h1), pack2(h2, h3));
        obl[d4] = make_uint2(pack2(l0, l1), pack2(l2, l3));
    }
}

// ---------------------------------------------------------------------------
// Launch
// ---------------------------------------------------------------------------
extern "C" void kernel_launch(void* const* d_in, const int* in_sizes, int n_in,
                              void* d_out, int out_size)
{
    const float* feat   = (const float*)d_in[0];
    const float* w_qkv  = (const float*)d_in[1];
    const float* b_qkv  = (const float*)d_in[2];
    const float* w_proj = (const float*)d_in[3];
    const float* b_proj = (const float*)d_in[4];
    const float* rpe    = (const float*)d_in[5];
    const int*   gcoord = (const int*)d_in[6];
    const int*   order  = (const int*)d_in[7];
    float* out = (float*)d_out;

    float *qkv_buf = nullptr;
    __nv_bfloat16 *fh, *fl, *ah, *al, *qh, *ql, *ph, *pl;
    cudaGetSymbolAddress((void**)&qkv_buf, g_qkv);
    cudaGetSymbolAddress((void**)&fh, g_feat_hi);
    cudaGetSymbolAddress((void**)&fl, g_feat_lo);
    cudaGetSymbolAddress((void**)&ah, g_attn_hi);
    cudaGetSymbolAddress((void**)&al, g_attn_lo);
    cudaGetSymbolAddress((void**)&qh, g_wqkv_hi);
    cudaGetSymbolAddress((void**)&ql, g_wqkv_lo);
    cudaGetSymbolAddress((void**)&ph, g_wproj_hi);
    cudaGetSymbolAddress((void**)&pl, g_wproj_lo);

    // fp32 -> bf16 hi/lo splits
    split_bf16_kernel<<<2048, 256>>>((const float4*)feat,  (uint2*)fh, (uint2*)fl, N_PTS * C_DIM / 4);
    split_bf16_kernel<<<768, 256>>>((const float4*)w_qkv,  (uint2*)qh, (uint2*)ql, 3 * C_DIM * C_DIM / 4);
    split_bf16_kernel<<<256, 256>>>((const float4*)w_proj, (uint2*)ph, (uint2*)pl, C_DIM * C_DIM / 4);

    // 1) QKV projection with fused gather (HMMA tensor cores)
    gemm_tc_kernel<<<dim3(3 * C_DIM / NTL, N_PTS / MT), 256, SMEM_DYN>>>(
        fh, fl, qh, ql, b_qkv, qkv_buf, 3 * C_DIM, order);

    // 2) Windowed attention + RPE + softmax; epilogue writes bf16 hi/lo, point order
    attn_kernel<<<W_WIN * H_HEADS, 128>>>(qkv_buf, gcoord, order, rpe);

    // 3) Output projection (HMMA tensor cores)
    gemm_tc_kernel<<<dim3(C_DIM / NTL, N_PTS / MT), 256, SMEM_DYN>>>(
        ah, al, ph, pl, b_proj, out, C_DIM, nullptr);
}

// round 6
// speedup vs baseline: 1.8220x; 1.0178x over previous
#include <cuda_runtime.h>
#include <cuda_bf16.h>
#include <cstdint>

// ---------------------------------------------------------------------------
// Problem constants
// ---------------------------------------------------------------------------
#define N_PTS   65536
#define C_DIM   512
#define H_HEADS 8
#define P_WIN   128
#define DHEAD   64
#define W_WIN   (N_PTS / P_WIN)
#define RPE_NUM 31
#define POS_BND 15
#define SCALE_F 0.125f

// GEMM tiling (mma.sync HMMA path; tcgen05 unavailable: harness targets sm_100 base)
#define MT   128
#define NTL  128
#define BK   16            // bf16 elems per K chunk (32 B/row)
#define KTOT 512
#define NCHUNK (KTOT / BK) // 32
#define STAGES 3
// XOR-swizzled tiles: 128 rows x 32B, no padding -> 4096 B per tile
#define OFF_AH 0
#define OFF_AL 4096
#define OFF_BH 8192
#define OFF_BL 12288
#define STAGE_BYTES 16384
#define SMEM_DYN (STAGES * STAGE_BYTES)   // 49152 = 48KB, no FuncSetAttribute needed

// ---------------------------------------------------------------------------
// Scratch (device globals: allocation-free)
// ---------------------------------------------------------------------------
__device__ float g_qkv[(size_t)N_PTS * 3 * C_DIM];                       // serialized [N, 3C]
__device__ __align__(16) __nv_bfloat16 g_feat_hi[(size_t)N_PTS * C_DIM];
__device__ __align__(16) __nv_bfloat16 g_feat_lo[(size_t)N_PTS * C_DIM];
__device__ __align__(16) __nv_bfloat16 g_attn_hi[(size_t)N_PTS * C_DIM]; // point order
__device__ __align__(16) __nv_bfloat16 g_attn_lo[(size_t)N_PTS * C_DIM];
__device__ __align__(16) __nv_bfloat16 g_wqkv_hi[3 * C_DIM * C_DIM];
__device__ __align__(16) __nv_bfloat16 g_wqkv_lo[3 * C_DIM * C_DIM];
__device__ __align__(16) __nv_bfloat16 g_wproj_hi[C_DIM * C_DIM];
__device__ __align__(16) __nv_bfloat16 g_wproj_lo[C_DIM * C_DIM];

// ---------------------------------------------------------------------------
// Helpers
// ---------------------------------------------------------------------------
__device__ __forceinline__ uint32_t smem_u32(const void* p) {
    uint32_t a;
    asm("{ .reg .u64 t; cvta.to.shared.u64 t, %1; cvt.u32.u64 %0, t; }" : "=r"(a) : "l"(p));
    return a;
}
__device__ __forceinline__ void cp16(uint32_t dst, const void* src) {
    asm volatile("cp.async.cg.shared.global [%0], [%1], 16;" :: "r"(dst), "l"(src));
}
__device__ __forceinline__ void cp_commit() { asm volatile("cp.async.commit_group;" ::: "memory"); }
template <int NN>
__device__ __forceinline__ void cp_wait() { asm volatile("cp.async.wait_group %0;" :: "n"(NN) : "memory"); }

// ldmatrix x4: four 8x8 b16 matrices; lane l supplies row addr (matrix l>>3, row l&7)
__device__ __forceinline__ void ldsm4(uint32_t* d, uint32_t addr) {
    asm volatile("ldmatrix.sync.aligned.m8n8.x4.shared.b16 {%0,%1,%2,%3}, [%4];"
                 : "=r"(d[0]), "=r"(d[1]), "=r"(d[2]), "=r"(d[3]) : "r"(addr));
}

// mma.sync m16n8k16 bf16 -> f32, accumulate in place
__device__ __forceinline__ void mma16816(float* c, const uint32_t* a, const uint32_t* b) {
    asm volatile(
        "mma.sync.aligned.m16n8k16.row.col.f32.bf16.bf16.f32 "
        "{%0,%1,%2,%3}, {%4,%5,%6,%7}, {%8,%9}, {%0,%1,%2,%3};"
        : "+f"(c[0]), "+f"(c[1]), "+f"(c[2]), "+f"(c[3])
        : "r"(a[0]), "r"(a[1]), "r"(a[2]), "r"(a[3]), "r"(b[0]), "r"(b[1]));
}

__device__ __forceinline__ uint32_t pack2(__nv_bfloat16 a, __nv_bfloat16 b) {
    return (uint32_t)__bfloat16_as_ushort(a) | ((uint32_t)__bfloat16_as_ushort(b) << 16);
}

// ---------------------------------------------------------------------------
// fp32 -> bf16 hi/lo split
// ---------------------------------------------------------------------------
__global__ void split_bf16_kernel(const float4* __restrict__ src,
                                  uint2* __restrict__ hi, uint2* __restrict__ lo, int n4)
{
    for (int i = blockIdx.x * blockDim.x + threadIdx.x; i < n4; i += gridDim.x * blockDim.x) {
        float4 v = src[i];
        __nv_bfloat16 h0 = __float2bfloat16(v.x), h1 = __float2bfloat16(v.y);
        __nv_bfloat16 h2 = __float2bfloat16(v.z), h3 = __float2bfloat16(v.w);
        __nv_bfloat16 l0 = __float2bfloat16(v.x - __bfloat162float(h0));
        __nv_bfloat16 l1 = __float2bfloat16(v.y - __bfloat162float(h1));
        __nv_bfloat16 l2 = __float2bfloat16(v.z - __bfloat162float(h2));
        __nv_bfloat16 l3 = __float2bfloat16(v.w - __bfloat162float(h3));
        hi[i] = make_uint2(pack2(h0, h1), pack2(h2, h3));
        lo[i] = make_uint2(pack2(l0, l1), pack2(l2, l3));
    }
}

// ---------------------------------------------------------------------------
// HMMA split-bf16 GEMM (NT): C[m,n] = sum_k A[g(m),k]*B[n,k] + bias[n]
// 128x128 CTA tile, BK=16, 256 threads (8 warps, 2M x 4N), warp tile 64x32.
// 3-stage cp.async pipeline, XOR-swizzled smem, ldmatrix fragment loads.
// 3 products: AhBh + AhBl + AlBh.
// ---------------------------------------------------------------------------
__device__ __forceinline__ void load_chunk(
    uint32_t stagebase, int kc, int t, int arow, int brow,
    const __nv_bfloat16* __restrict__ Ah, const __nv_bfloat16* __restrict__ Al,
    const __nv_bfloat16* __restrict__ Bh, const __nv_bfloat16* __restrict__ Bl)
{
    // per tile: 128 rows x 2 granules of 16B = 256 granules; 1 per thread
    const int g16 = t & 1;                 // 0..1 (16B half within 32B row)
    const int r   = t >> 1;                // 0..127
    const uint32_t soff = (uint32_t)(r * 32) + (uint32_t)((g16 ^ ((r >> 2) & 1)) * 16);
    const size_t goffA = (size_t)arow * KTOT + kc * BK + g16 * 8;
    const size_t goffB = (size_t)brow * KTOT + kc * BK + g16 * 8;
    cp16(stagebase + OFF_AH + soff, Ah + goffA);
    cp16(stagebase + OFF_AL + soff, Al + goffA);
    cp16(stagebase + OFF_BH + soff, Bh + goffB);
    cp16(stagebase + OFF_BL + soff, Bl + goffB);
}

__global__ void __launch_bounds__(256) gemm_tc_kernel(
    const __nv_bfloat16* __restrict__ Ah, const __nv_bfloat16* __restrict__ Al,
    const __nv_bfloat16* __restrict__ Bh, const __nv_bfloat16* __restrict__ Bl,
    const float* __restrict__ bias, float* __restrict__ C,
    int Nglob, const int* __restrict__ gather)
{
    extern __shared__ __align__(16) char dsm[];
    const uint32_t sbase = smem_u32(dsm);
    const int t = threadIdx.x;
    const int bx = blockIdx.x, by = blockIdx.y;
    const int lane = t & 31, wid = t >> 5;
    const int wm = wid & 1;          // 0..1 -> 64-row slab
    const int wn = wid >> 1;         // 0..3 -> 32-col slab
    const int g  = lane >> 2;        // 0..7
    const int tg = lane & 3;         // 0..3

    // ldmatrix per-lane address component: row = base + (lane&15), h = lane>>4,
    // swizzled h' = h ^ ((row>>2)&1); bases are 16-aligned so row bit2 = lane_row bit2.
    const int lane_row = lane & 15;
    const uint32_t lswz = (uint32_t)(((lane >> 4) ^ ((lane_row >> 2) & 1)) * 16);
    const uint32_t aoff = (uint32_t)((wm * 64 + lane_row) * 32) + lswz;
    const uint32_t boff = (uint32_t)((wn * 32 + lane_row) * 32) + lswz;

    int m = by * MT + (t >> 1);
    const int arow = gather ? __ldg(gather + m) : m;
    const int brow = bx * NTL + (t >> 1);

    float acc[4][4][4];
#pragma unroll
    for (int i = 0; i < 4; ++i)
#pragma unroll
        for (int j = 0; j < 4; ++j)
#pragma unroll
            for (int e = 0; e < 4; ++e) acc[i][j][e] = 0.f;

    // Prologue: stages 0,1
    load_chunk(sbase, 0, t, arow, brow, Ah, Al, Bh, Bl);
    cp_commit();
    load_chunk(sbase + STAGE_BYTES, 1, t, arow, brow, Ah, Al, Bh, Bl);
    cp_commit();

    int su = 0, sl = 2;   // stage in use / stage to load
    for (int c = 0; c < NCHUNK; ++c) {
        if (c + 2 < NCHUNK) {
            load_chunk(sbase + sl * STAGE_BYTES, c + 2, t, arow, brow, Ah, Al, Bh, Bl);
            cp_commit();
            cp_wait<2>();          // chunk c's loads complete
        } else {
            cp_wait<0>();
        }
        __syncthreads();

        const uint32_t stb = sbase + su * STAGE_BYTES;

        // B fragments: 2 x ldmatrix.x4 per variant covers all 4 n-tiles
        uint32_t bh[4][2], bl[4][2];
#pragma unroll
        for (int jp = 0; jp < 2; ++jp) {
            uint32_t tmp[4];
            ldsm4(tmp, stb + OFF_BH + boff + jp * 512);
            bh[jp * 2][0] = tmp[0]; bh[jp * 2 + 1][0] = tmp[1];
            bh[jp * 2][1] = tmp[2]; bh[jp * 2 + 1][1] = tmp[3];
            ldsm4(tmp, stb + OFF_BL + boff + jp * 512);
            bl[jp * 2][0] = tmp[0]; bl[jp * 2 + 1][0] = tmp[1];
            bl[jp * 2][1] = tmp[2]; bl[jp * 2 + 1][1] = tmp[3];
        }
#pragma unroll
        for (int i = 0; i < 4; ++i) {
            uint32_t ah[4], al[4];
            ldsm4(ah, stb + OFF_AH + aoff + i * 512);
            ldsm4(al, stb + OFF_AL + aoff + i * 512);
#pragma unroll
            for (int j = 0; j < 4; ++j) {
                mma16816(acc[i][j], ah, bh[j]);
                mma16816(acc[i][j], ah, bl[j]);
                mma16816(acc[i][j], al, bh[j]);
            }
        }
        __syncthreads();   // all warps done with stage su before it is reloaded
        su = (su == STAGES - 1) ? 0 : su + 1;
        sl = (sl == STAGES - 1) ? 0 : sl + 1;
    }

    // Epilogue: c frag layout rows {g, g+8}, cols {tg*2, tg*2+1}
#pragma unroll
    for (int i = 0; i < 4; ++i) {
        const int row0 = by * MT + wm * 64 + i * 16 + g;
#pragma unroll
        for (int j = 0; j < 4; ++j) {
            const int col = bx * NTL + wn * 32 + j * 8 + tg * 2;
            const float b0 = __ldg(bias + col), b1 = __ldg(bias + col + 1);
            float2 v0 = make_float2(acc[i][j][0] + b0, acc[i][j][1] + b1);
            float2 v1 = make_float2(acc[i][j][2] + b0, acc[i][j][3] + b1);
            *(float2*)(C + (size_t)row0 * Nglob + col) = v0;
            *(float2*)(C + (size_t)(row0 + 8) * Nglob + col) = v1;
        }
    }
}

// ---------------------------------------------------------------------------
// Windowed attention with RPE; epilogue writes bf16 hi/lo in point order.
// ---------------------------------------------------------------------------
__global__ void __launch_bounds__(128) attn_kernel(
    const float* __restrict__ qkv,        // [N, 3C] serialized
    const int*   __restrict__ grid_coord, // [N, 3] point order
    const int*   __restrict__ order,      // [N]
    const float* __restrict__ rpe)        // [3*RPE_NUM, H]
{
    const int w = blockIdx.x >> 3;
    const int h = blockIdx.x & 7;
    const int p = threadIdx.x;

    __shared__ __align__(16) float ks[32][64];
    __shared__ __align__(16) float vs[32][64];
    __shared__ int   gcs[P_WIN][3];
    __shared__ float rpe_s[3 * RPE_NUM];

    const int r = w * P_WIN + p;
    const int o = order[r];

    const int gx = grid_coord[o * 3 + 0];
    const int gy = grid_coord[o * 3 + 1];
    const int gz = grid_coord[o * 3 + 2];
    gcs[p][0] = gx; gcs[p][1] = gy; gcs[p][2] = gz;
    if (p < 3 * RPE_NUM) rpe_s[p] = rpe[p * H_HEADS + h];

    float q[64];
    {
        const float* qb = qkv + (size_t)r * (3 * C_DIM) + h * DHEAD;
#pragma unroll
        for (int d4 = 0; d4 < 16; ++d4) {
            float4 v = *(const float4*)(qb + d4 * 4);
            q[d4 * 4 + 0] = v.x * SCALE_F;
            q[d4 * 4 + 1] = v.y * SCALE_F;
            q[d4 * 4 + 2] = v.z * SCALE_F;
            q[d4 * 4 + 3] = v.w * SCALE_F;
        }
    }

    float m = -1e30f, l = 0.f;
    float out[64];
#pragma unroll
    for (int d = 0; d < 64; ++d) out[d] = 0.f;

    for (int c = 0; c < 4; ++c) {
        __syncthreads();
#pragma unroll
        for (int i = 0; i < 4; ++i) {
            int idx = i * 128 + p;
            int row = idx >> 4;
            int c4  = idx & 15;
            const float* kb = qkv + (size_t)(w * P_WIN + c * 32 + row) * (3 * C_DIM)
                            + C_DIM + h * DHEAD + c4 * 4;
            *(float4*)&ks[row][c4 * 4] = *(const float4*)kb;
            *(float4*)&vs[row][c4 * 4] = *(const float4*)(kb + C_DIM);
        }
        __syncthreads();

        for (int j = 0; j < 32; ++j) {
            const int kidx = c * 32 + j;
            int dx = gx - gcs[kidx][0];
            int dy = gy - gcs[kidx][1];
            int dz = gz - gcs[kidx][2];
            dx = min(max(dx, -POS_BND), POS_BND) + POS_BND;
            dy = min(max(dy, -POS_BND), POS_BND) + POS_BND;
            dz = min(max(dz, -POS_BND), POS_BND) + POS_BND;
            float s = rpe_s[dx] + rpe_s[RPE_NUM + dy] + rpe_s[2 * RPE_NUM + dz];
#pragma unroll
            for (int d4 = 0; d4 < 16; ++d4) {
                float4 kv = *(const float4*)&ks[j][d4 * 4];
                s += q[d4 * 4 + 0] * kv.x + q[d4 * 4 + 1] * kv.y
                   + q[d4 * 4 + 2] * kv.z + q[d4 * 4 + 3] * kv.w;
            }
            float pj;
            if (s <= m) {
                pj = __expf(s - m);
            } else {
                float corr = __expf(m - s);
                l *= corr;
#pragma unroll
                for (int d = 0; d < 64; ++d) out[d] *= corr;
                m = s;
                pj = 1.f;
            }
            l += pj;
#pragma unroll
            for (int d4 = 0; d4 < 16; ++d4) {
                float4 vv = *(const float4*)&vs[j][d4 * 4];
                out[d4 * 4 + 0] += pj * vv.x;
                out[d4 * 4 + 1] += pj * vv.y;
                out[d4 * 4 + 2] += pj * vv.z;
                out[d4 * 4 + 3] += pj * vv.w;
            }
        }
    }

    const float inv = 1.f / l;
    uint2* obh = (uint2*)(g_attn_hi + (size_t)o * C_DIM + h * DHEAD);
    uint2* obl = (uint2*)(g_attn_lo + (size_t)o * C_DIM + h * DHEAD);
#pragma unroll
    for (int d4 = 0; d4 < 16; ++d4) {
        float v0 = out[d4 * 4 + 0] * inv;
        float v1 = out[d4 * 4 + 1] * inv;
        float v2 = out[d4 * 4 + 2] * inv;
        float v3 = out[d4 * 4 + 3] * inv;
        __nv_bfloat16 h0 = __float2bfloat16(v0), h1 = __float2bfloat16(v1);
        __nv_bfloat16 h2 = __float2bfloat16(v2), h3 = __float2bfloat16(v3);
        __nv_bfloat16 l0 = __float2bfloat16(v0 - __bfloat162float(h0));
        __nv_bfloat16 l1 = __float2bfloat16(v1 - __bfloat162float(h1));
        __nv_bfloat16 l2 = __float2bfloat16(v2 - __bfloat162float(h2));
        __nv_bfloat16 l3 = __float2bfloat16(v3 - __bfloat162float(h3));
        obh[d4] = make_uint2(pack2(h0, h1), pack2(h2, h3));
        obl[d4] = make_uint2(pack2(l0, l1), pack2(l2, l3));
    }
}

// ---------------------------------------------------------------------------
// Launch
// ---------------------------------------------------------------------------
extern "C" void kernel_launch(void* const* d_in, const int* in_sizes, int n_in,
                              void* d_out, int out_size)
{
    const float* feat   = (const float*)d_in[0];
    const float* w_qkv  = (const float*)d_in[1];
    const float* b_qkv  = (const float*)d_in[2];
    const float* w_proj = (const float*)d_in[3];
    const float* b_proj = (const float*)d_in[4];
    const float* rpe    = (const float*)d_in[5];
    const int*   gcoord = (const int*)d_in[6];
    const int*   order  = (const int*)d_in[7];
    float* out = (float*)d_out;

    float *qkv_buf = nullptr;
    __nv_bfloat16 *fh, *fl, *ah, *al, *qh, *ql, *ph, *pl;
    cudaGetSymbolAddress((void**)&qkv_buf, g_qkv);
    cudaGetSymbolAddress((void**)&fh, g_feat_hi);
    cudaGetSymbolAddress((void**)&fl, g_feat_lo);
    cudaGetSymbolAddress((void**)&ah, g_attn_hi);
    cudaGetSymbolAddress((void**)&al, g_attn_lo);
    cudaGetSymbolAddress((void**)&qh, g_wqkv_hi);
    cudaGetSymbolAddress((void**)&ql, g_wqkv_lo);
    cudaGetSymbolAddress((void**)&ph, g_wproj_hi);
    cudaGetSymbolAddress((void**)&pl, g_wproj_lo);

    // fp32 -> bf16 hi/lo splits
    split_bf16_kernel<<<2048, 256>>>((const float4*)feat,  (uint2*)fh, (uint2*)fl, N_PTS * C_DIM / 4);
    split_bf16_kernel<<<768, 256>>>((const float4*)w_qkv,  (uint2*)qh, (uint2*)ql, 3 * C_DIM * C_DIM / 4);
    split_bf16_kernel<<<256, 256>>>((const float4*)w_proj, (uint2*)ph, (uint2*)pl, C_DIM * C_DIM / 4);

    // 1) QKV projection with fused gather (HMMA tensor cores)
    gemm_tc_kernel<<<dim3(3 * C_DIM / NTL, N_PTS / MT), 256, SMEM_DYN>>>(
        fh, fl, qh, ql, b_qkv, qkv_buf, 3 * C_DIM, order);

    // 2) Windowed attention + RPE + softmax; epilogue writes bf16 hi/lo, point order
    attn_kernel<<<W_WIN * H_HEADS, 128>>>(qkv_buf, gcoord, order, rpe);

    // 3) Output projection (HMMA tensor cores)
    gemm_tc_kernel<<<dim3(C_DIM / NTL, N_PTS / MT), 256, SMEM_DYN>>>(
        ah, al, ph, pl, b_proj, out, C_DIM, nullptr);
}